// round 1
// baseline (speedup 1.0000x reference)
#include <cuda_runtime.h>
#include <math.h>

// Problem constants
#define B_ 2
#define S_ 2048
#define D_ 1024
#define H_ 16
#define DK_ 64

// ---------------- scratch (no cudaMalloc allowed) ----------------
__device__ float g_q[(size_t)B_ * S_ * D_];
__device__ float g_k[(size_t)B_ * S_ * D_];
__device__ float g_v[(size_t)B_ * S_ * D_];
__device__ float g_ctx[(size_t)B_ * S_ * D_];

// ---------------- SGEMM: C[M,N] = A[M,K] @ W[N,K]^T + bias[N] ----------------
// 128x128 block tile, BK=8, 256 threads, 8x8 register tile per thread.
__global__ __launch_bounds__(256) void sgemm_xwt(
    const float* __restrict__ A, const float* __restrict__ W,
    const float* __restrict__ bias, float* __restrict__ C,
    int M, int N, int K)
{
    __shared__ float As[8][128];
    __shared__ float Ws[8][128];

    int tid = threadIdx.x;
    int bm = blockIdx.y * 128;
    int bn = blockIdx.x * 128;
    int tx = tid & 15;      // 0..15
    int ty = tid >> 4;      // 0..15

    int lrow = tid >> 1;          // 0..127
    int lk4  = (tid & 1) * 4;     // 0 or 4

    const float* Aptr = A + (size_t)(bm + lrow) * K + lk4;
    const float* Wptr = W + (size_t)(bn + lrow) * K + lk4;

    float acc[8][8];
#pragma unroll
    for (int i = 0; i < 8; i++)
#pragma unroll
        for (int j = 0; j < 8; j++) acc[i][j] = 0.f;

    for (int k0 = 0; k0 < K; k0 += 8) {
        float4 av = *(const float4*)(Aptr + k0);
        float4 wv = *(const float4*)(Wptr + k0);
        As[lk4 + 0][lrow] = av.x;
        As[lk4 + 1][lrow] = av.y;
        As[lk4 + 2][lrow] = av.z;
        As[lk4 + 3][lrow] = av.w;
        Ws[lk4 + 0][lrow] = wv.x;
        Ws[lk4 + 1][lrow] = wv.y;
        Ws[lk4 + 2][lrow] = wv.z;
        Ws[lk4 + 3][lrow] = wv.w;
        __syncthreads();

#pragma unroll
        for (int kk = 0; kk < 8; kk++) {
            float a[8], w[8];
            *(float4*)&a[0] = *(const float4*)&As[kk][ty * 8];
            *(float4*)&a[4] = *(const float4*)&As[kk][ty * 8 + 4];
            *(float4*)&w[0] = *(const float4*)&Ws[kk][tx * 8];
            *(float4*)&w[4] = *(const float4*)&Ws[kk][tx * 8 + 4];
#pragma unroll
            for (int i = 0; i < 8; i++)
#pragma unroll
                for (int j = 0; j < 8; j++)
                    acc[i][j] += a[i] * w[j];
        }
        __syncthreads();
    }

#pragma unroll
    for (int i = 0; i < 8; i++) {
        float* crow = C + (size_t)(bm + ty * 8 + i) * N + bn + tx * 8;
#pragma unroll
        for (int j = 0; j < 8; j++)
            crow[j] = acc[i][j] + bias[bn + tx * 8 + j];
    }
}

// ---------------- fused attention ----------------
// One block = 8 query rows of one (b,h). Scores row (8 x 2048) lives in smem:
// compute QK^T, softmax in smem, write attn to gmem ONCE, then PV from smem.
#define AR 8          // query rows per block
#define KT 64         // kv tile (rows)
#define KV_LD (DK_ + 1)

__global__ __launch_bounds__(256) void attn_fused(
    const float* __restrict__ Qg, const float* __restrict__ Kg,
    const float* __restrict__ Vg, float* __restrict__ attn,
    float* __restrict__ ctx)
{
    extern __shared__ float sm[];
    float* s_sc = sm;                        // AR * S_
    float* s_kv = sm + AR * S_;              // KT * KV_LD
    float* s_q  = s_kv + KT * KV_LD;         // AR * DK_

    int tid = threadIdx.x;
    int bh = blockIdx.y;                     // b*H + h
    int b  = bh >> 4;
    int h  = bh & 15;
    int q0 = blockIdx.x * AR;

    const size_t base = (size_t)b * S_ * D_ + (size_t)h * DK_;

    // load Q rows (8 x 64)
    for (int i = tid; i < AR * DK_; i += 256) {
        int r = i >> 6, d = i & 63;
        s_q[i] = Qg[base + (size_t)(q0 + r) * D_ + d];
    }

    int c  = tid & 63;       // column within kv tile
    int rr = tid >> 6;       // 0..3  (handles rows rr and rr+4)

    // ---- scores = Q @ K^T * scale ----
    for (int kt = 0; kt < S_; kt += KT) {
        __syncthreads();  // protect s_kv reuse + first-iter s_q visibility
        for (int i = tid; i < KT * (DK_ / 4); i += 256) {
            int row  = i >> 4;             // /16
            int col4 = (i & 15) * 4;
            float4 v = *(const float4*)&Kg[base + (size_t)(kt + row) * D_ + col4];
            float* dst = &s_kv[row * KV_LD + col4];
            dst[0] = v.x; dst[1] = v.y; dst[2] = v.z; dst[3] = v.w;
        }
        __syncthreads();

        float a0 = 0.f, a1 = 0.f;
#pragma unroll 16
        for (int d = 0; d < DK_; d++) {
            float kv = s_kv[c * KV_LD + d];
            a0 += s_q[rr * DK_ + d] * kv;
            a1 += s_q[(rr + 4) * DK_ + d] * kv;
        }
        s_sc[rr * S_ + kt + c]       = a0 * 0.125f;   // 1/sqrt(64)
        s_sc[(rr + 4) * S_ + kt + c] = a1 * 0.125f;
    }
    __syncthreads();

    // ---- softmax per row (32 threads per row), write attn once ----
    {
        int r = tid >> 5, lane = tid & 31;
        float* row = &s_sc[r * S_];
        float mx = -1e30f;
        for (int j = lane; j < S_; j += 32) mx = fmaxf(mx, row[j]);
#pragma unroll
        for (int o = 16; o > 0; o >>= 1) mx = fmaxf(mx, __shfl_xor_sync(0xffffffffu, mx, o));
        float sum = 0.f;
        for (int j = lane; j < S_; j += 32) {
            float e = __expf(row[j] - mx);
            row[j] = e;
            sum += e;
        }
#pragma unroll
        for (int o = 16; o > 0; o >>= 1) sum += __shfl_xor_sync(0xffffffffu, sum, o);
        float inv = 1.f / sum;
        float* arow = attn + ((size_t)bh * S_ + (q0 + r)) * S_;
        for (int j = lane; j < S_; j += 32) {
            float p = row[j] * inv;
            row[j] = p;
            arow[j] = p;
        }
    }

    // ---- ctx = P @ V ----
    int d = tid & 63;
    float c0 = 0.f, c1 = 0.f;
    for (int vt = 0; vt < S_; vt += KT) {
        __syncthreads();
        for (int i = tid; i < KT * (DK_ / 4); i += 256) {
            int row  = i >> 4;
            int col4 = (i & 15) * 4;
            float4 v = *(const float4*)&Vg[base + (size_t)(vt + row) * D_ + col4];
            float* dst = &s_kv[row * KV_LD + col4];
            dst[0] = v.x; dst[1] = v.y; dst[2] = v.z; dst[3] = v.w;
        }
        __syncthreads();

#pragma unroll 16
        for (int cc = 0; cc < KT; cc++) {
            float vv = s_kv[cc * KV_LD + d];
            c0 += s_sc[rr * S_ + vt + cc] * vv;
            c1 += s_sc[(rr + 4) * S_ + vt + cc] * vv;
        }
    }
    // merged-heads layout: ctx[(b*S + q)*D + h*DK + d]
    ctx[base + (size_t)(q0 + rr) * D_ + d]     = c0;
    ctx[base + (size_t)(q0 + rr + 4) * D_ + d] = c1;
}

// ---------------- launch ----------------
extern "C" void kernel_launch(void* const* d_in, const int* in_sizes, int n_in,
                              void* d_out, int out_size)
{
    const float* query = (const float*)d_in[0];
    const float* key   = (const float*)d_in[1];
    const float* value = (const float*)d_in[2];
    const float* Wq    = (const float*)d_in[3];
    const float* bq    = (const float*)d_in[4];
    const float* Wk    = (const float*)d_in[5];
    const float* bk    = (const float*)d_in[6];
    const float* Wv    = (const float*)d_in[7];
    const float* bv    = (const float*)d_in[8];
    const float* Wo    = (const float*)d_in[9];
    const float* bo    = (const float*)d_in[10];

    float* out  = (float*)d_out;                          // (B,S,D)
    float* attn = out + (size_t)B_ * S_ * D_;             // (B,H,S,S)

    float *q, *k, *v, *ctx;
    cudaGetSymbolAddress((void**)&q,   g_q);
    cudaGetSymbolAddress((void**)&k,   g_k);
    cudaGetSymbolAddress((void**)&v,   g_v);
    cudaGetSymbolAddress((void**)&ctx, g_ctx);

    const int M = B_ * S_;   // 4096
    const int N = D_;        // 1024
    const int K = D_;        // 1024
    dim3 ggrid(N / 128, M / 128);

    sgemm_xwt<<<ggrid, 256>>>(query, Wq, bq, q, M, N, K);
    sgemm_xwt<<<ggrid, 256>>>(key,   Wk, bk, k, M, N, K);
    sgemm_xwt<<<ggrid, 256>>>(value, Wv, bv, v, M, N, K);

    size_t smem = (size_t)(AR * S_ + KT * KV_LD + AR * DK_) * sizeof(float);
    cudaFuncSetAttribute(attn_fused, cudaFuncAttributeMaxDynamicSharedMemorySize, (int)smem);
    dim3 agrid(S_ / AR, B_ * H_);
    attn_fused<<<agrid, 256, smem>>>(q, k, v, attn, ctx);

    sgemm_xwt<<<ggrid, 256>>>(ctx, Wo, bo, out, M, N, K);
}

// round 2
// speedup vs baseline: 2.4393x; 2.4393x over previous
#include <cuda_runtime.h>
#include <math.h>

// Problem constants
#define B_ 2
#define S_ 2048
#define D_ 1024
#define H_ 16
#define DK_ 64

// ---------------- scratch (no cudaMalloc allowed) ----------------
__device__ float g_q[(size_t)B_ * S_ * D_];
__device__ float g_k[(size_t)B_ * S_ * D_];
__device__ float g_v[(size_t)B_ * S_ * D_];
__device__ float g_ctx[(size_t)B_ * S_ * D_];

// ---------------- SGEMM: C[M,N] = A[M,K] @ W[N,K]^T + bias[N] ----------------
// 128x128 block tile, BK=8, 256 threads, 8x8 register tile per thread.
__global__ __launch_bounds__(256) void sgemm_xwt(
    const float* __restrict__ A, const float* __restrict__ W,
    const float* __restrict__ bias, float* __restrict__ C,
    int M, int N, int K)
{
    __shared__ float As[8][128];
    __shared__ float Ws[8][128];

    int tid = threadIdx.x;
    int bm = blockIdx.y * 128;
    int bn = blockIdx.x * 128;
    int tx = tid & 15;      // 0..15
    int ty = tid >> 4;      // 0..15

    int lrow = tid >> 1;          // 0..127
    int lk4  = (tid & 1) * 4;     // 0 or 4

    const float* Aptr = A + (size_t)(bm + lrow) * K + lk4;
    const float* Wptr = W + (size_t)(bn + lrow) * K + lk4;

    float acc[8][8];
#pragma unroll
    for (int i = 0; i < 8; i++)
#pragma unroll
        for (int j = 0; j < 8; j++) acc[i][j] = 0.f;

    for (int k0 = 0; k0 < K; k0 += 8) {
        float4 av = *(const float4*)(Aptr + k0);
        float4 wv = *(const float4*)(Wptr + k0);
        As[lk4 + 0][lrow] = av.x;
        As[lk4 + 1][lrow] = av.y;
        As[lk4 + 2][lrow] = av.z;
        As[lk4 + 3][lrow] = av.w;
        Ws[lk4 + 0][lrow] = wv.x;
        Ws[lk4 + 1][lrow] = wv.y;
        Ws[lk4 + 2][lrow] = wv.z;
        Ws[lk4 + 3][lrow] = wv.w;
        __syncthreads();

#pragma unroll
        for (int kk = 0; kk < 8; kk++) {
            float a[8], w[8];
            *(float4*)&a[0] = *(const float4*)&As[kk][ty * 8];
            *(float4*)&a[4] = *(const float4*)&As[kk][ty * 8 + 4];
            *(float4*)&w[0] = *(const float4*)&Ws[kk][tx * 8];
            *(float4*)&w[4] = *(const float4*)&Ws[kk][tx * 8 + 4];
#pragma unroll
            for (int i = 0; i < 8; i++)
#pragma unroll
                for (int j = 0; j < 8; j++)
                    acc[i][j] += a[i] * w[j];
        }
        __syncthreads();
    }

    float bv[8];
#pragma unroll
    for (int j = 0; j < 8; j++) bv[j] = bias[bn + tx * 8 + j];

#pragma unroll
    for (int i = 0; i < 8; i++) {
        float* crow = C + (size_t)(bm + ty * 8 + i) * N + bn + tx * 8;
        float4 o0, o1;
        o0.x = acc[i][0] + bv[0]; o0.y = acc[i][1] + bv[1];
        o0.z = acc[i][2] + bv[2]; o0.w = acc[i][3] + bv[3];
        o1.x = acc[i][4] + bv[4]; o1.y = acc[i][5] + bv[5];
        o1.z = acc[i][6] + bv[6]; o1.w = acc[i][7] + bv[7];
        *(float4*)&crow[0] = o0;
        *(float4*)&crow[4] = o1;
    }
}

// ---------------- QK^T scores (raw, scaled) ----------------
// Per (b,h): scores[2048,2048] = 0.125 * q_hat @ k_hat^T
// Same 128x128 / 8x8-per-thread register tiling; K=64, row stride D_.
__global__ __launch_bounds__(256) void qk_scores(
    const float* __restrict__ Qg, const float* __restrict__ Kg,
    float* __restrict__ attn)
{
    __shared__ float As[8][128];
    __shared__ float Bs[8][128];

    int tid = threadIdx.x;
    int bm = blockIdx.y * 128;
    int bn = blockIdx.x * 128;
    int bh = blockIdx.z;                  // b*H + h
    int b  = bh >> 4;
    int h  = bh & 15;
    const size_t base = (size_t)b * S_ * D_ + (size_t)h * DK_;

    int tx = tid & 15;
    int ty = tid >> 4;
    int lrow = tid >> 1;
    int lk4  = (tid & 1) * 4;

    const float* Aptr = Qg + base + (size_t)(bm + lrow) * D_ + lk4;
    const float* Bptr = Kg + base + (size_t)(bn + lrow) * D_ + lk4;

    float acc[8][8];
#pragma unroll
    for (int i = 0; i < 8; i++)
#pragma unroll
        for (int j = 0; j < 8; j++) acc[i][j] = 0.f;

    for (int k0 = 0; k0 < DK_; k0 += 8) {
        float4 av = *(const float4*)(Aptr + k0);
        float4 bvv = *(const float4*)(Bptr + k0);
        As[lk4 + 0][lrow] = av.x;
        As[lk4 + 1][lrow] = av.y;
        As[lk4 + 2][lrow] = av.z;
        As[lk4 + 3][lrow] = av.w;
        Bs[lk4 + 0][lrow] = bvv.x;
        Bs[lk4 + 1][lrow] = bvv.y;
        Bs[lk4 + 2][lrow] = bvv.z;
        Bs[lk4 + 3][lrow] = bvv.w;
        __syncthreads();

#pragma unroll
        for (int kk = 0; kk < 8; kk++) {
            float a[8], w[8];
            *(float4*)&a[0] = *(const float4*)&As[kk][ty * 8];
            *(float4*)&a[4] = *(const float4*)&As[kk][ty * 8 + 4];
            *(float4*)&w[0] = *(const float4*)&Bs[kk][tx * 8];
            *(float4*)&w[4] = *(const float4*)&Bs[kk][tx * 8 + 4];
#pragma unroll
            for (int i = 0; i < 8; i++)
#pragma unroll
                for (int j = 0; j < 8; j++)
                    acc[i][j] += a[i] * w[j];
        }
        __syncthreads();
    }

    float* C = attn + (size_t)bh * S_ * S_;
#pragma unroll
    for (int i = 0; i < 8; i++) {
        float* crow = C + (size_t)(bm + ty * 8 + i) * S_ + bn + tx * 8;
        float4 o0, o1;
        o0.x = acc[i][0] * 0.125f; o0.y = acc[i][1] * 0.125f;
        o0.z = acc[i][2] * 0.125f; o0.w = acc[i][3] * 0.125f;
        o1.x = acc[i][4] * 0.125f; o1.y = acc[i][5] * 0.125f;
        o1.z = acc[i][6] * 0.125f; o1.w = acc[i][7] * 0.125f;
        *(float4*)&crow[0] = o0;
        *(float4*)&crow[4] = o1;
    }
}

// ---------------- streaming row softmax (in place) ----------------
// One block = one row of 2048 floats. 256 threads, 8 elems each.
__global__ __launch_bounds__(256) void softmax_rows(float* __restrict__ attn)
{
    __shared__ float redmax[8];
    __shared__ float redsum[8];

    size_t row = blockIdx.x;
    float* p = attn + row * (size_t)S_;
    int tid = threadIdx.x;
    int lane = tid & 31, warp = tid >> 5;

    float4 v0 = ((const float4*)p)[tid];
    float4 v1 = ((const float4*)p)[tid + 256];

    float mx = fmaxf(fmaxf(fmaxf(v0.x, v0.y), fmaxf(v0.z, v0.w)),
                     fmaxf(fmaxf(v1.x, v1.y), fmaxf(v1.z, v1.w)));
#pragma unroll
    for (int o = 16; o > 0; o >>= 1)
        mx = fmaxf(mx, __shfl_xor_sync(0xffffffffu, mx, o));
    if (lane == 0) redmax[warp] = mx;
    __syncthreads();
    mx = redmax[0];
#pragma unroll
    for (int w = 1; w < 8; w++) mx = fmaxf(mx, redmax[w]);

    v0.x = __expf(v0.x - mx); v0.y = __expf(v0.y - mx);
    v0.z = __expf(v0.z - mx); v0.w = __expf(v0.w - mx);
    v1.x = __expf(v1.x - mx); v1.y = __expf(v1.y - mx);
    v1.z = __expf(v1.z - mx); v1.w = __expf(v1.w - mx);

    float sum = (v0.x + v0.y) + (v0.z + v0.w) + (v1.x + v1.y) + (v1.z + v1.w);
#pragma unroll
    for (int o = 16; o > 0; o >>= 1)
        sum += __shfl_xor_sync(0xffffffffu, sum, o);
    if (lane == 0) redsum[warp] = sum;
    __syncthreads();
    sum = redsum[0];
#pragma unroll
    for (int w = 1; w < 8; w++) sum += redsum[w];

    float inv = 1.f / sum;
    v0.x *= inv; v0.y *= inv; v0.z *= inv; v0.w *= inv;
    v1.x *= inv; v1.y *= inv; v1.z *= inv; v1.w *= inv;

    ((float4*)p)[tid]       = v0;
    ((float4*)p)[tid + 256] = v1;
}

// ---------------- PV: ctx = P @ v_hat ----------------
// Per (b,h): C[2048,64] = P[2048,2048] @ V[2048,64].
// Block tile 128(M) x 64(N), BK=32, 256 threads, 8x4 per thread.
#define PV_BK 32
#define PS_LD 132

__global__ __launch_bounds__(256) void pv_gemm(
    const float* __restrict__ attn, const float* __restrict__ Vg,
    float* __restrict__ ctx)
{
    __shared__ float Ps[PV_BK][PS_LD];   // [k][m]
    __shared__ float Vs[PV_BK][64];      // [k][n]

    int tid = threadIdx.x;
    int bh = blockIdx.y;
    int b  = bh >> 4;
    int h  = bh & 15;
    int bm = blockIdx.x * 128;

    const float* P = attn + (size_t)bh * S_ * S_ + (size_t)bm * S_;
    const float* V = Vg + (size_t)b * S_ * D_ + (size_t)h * DK_;
    float* Cc = ctx + (size_t)b * S_ * D_ + (size_t)h * DK_ + (size_t)bm * D_;

    int tx = tid & 15;     // n-group: cols tx*4
    int ty = tid >> 4;     // m-group: rows ty*8

    int prow = tid >> 1;            // 0..127
    int pk16 = (tid & 1) * 16;      // 0 or 16
    const float* Pptr = P + (size_t)prow * S_ + pk16;

    int vrow = tid >> 3;            // 0..31
    int vc   = (tid & 7) * 4;       // 0..28
    const float* Vptr = V + (size_t)vrow * D_ + vc;

    float acc[8][4];
#pragma unroll
    for (int i = 0; i < 8; i++)
#pragma unroll
        for (int j = 0; j < 4; j++) acc[i][j] = 0.f;

    for (int k0 = 0; k0 < S_; k0 += PV_BK) {
        // load P tile [128 x 32], store transposed
#pragma unroll
        for (int f = 0; f < 4; f++) {
            float4 u = *(const float4*)(Pptr + k0 + f * 4);
            int kb = pk16 + f * 4;
            Ps[kb + 0][prow] = u.x;
            Ps[kb + 1][prow] = u.y;
            Ps[kb + 2][prow] = u.z;
            Ps[kb + 3][prow] = u.w;
        }
        // load V tile [32 x 64]
        {
            float4 u = *(const float4*)(Vptr + (size_t)k0 * D_);
            *(float4*)&Vs[vrow][vc] = u;
            float4 u2 = *(const float4*)(Vptr + (size_t)k0 * D_ + 32);
            *(float4*)&Vs[vrow][vc + 32] = u2;
        }
        __syncthreads();

#pragma unroll
        for (int kk = 0; kk < PV_BK; kk++) {
            float a[8], w[4];
            *(float4*)&a[0] = *(const float4*)&Ps[kk][ty * 8];
            *(float4*)&a[4] = *(const float4*)&Ps[kk][ty * 8 + 4];
            *(float4*)&w[0] = *(const float4*)&Vs[kk][tx * 4];
#pragma unroll
            for (int i = 0; i < 8; i++)
#pragma unroll
                for (int j = 0; j < 4; j++)
                    acc[i][j] += a[i] * w[j];
        }
        __syncthreads();
    }

#pragma unroll
    for (int i = 0; i < 8; i++) {
        float4 o;
        o.x = acc[i][0]; o.y = acc[i][1]; o.z = acc[i][2]; o.w = acc[i][3];
        *(float4*)&Cc[(size_t)(ty * 8 + i) * D_ + tx * 4] = o;
    }
}

// ---------------- launch ----------------
extern "C" void kernel_launch(void* const* d_in, const int* in_sizes, int n_in,
                              void* d_out, int out_size)
{
    const float* query = (const float*)d_in[0];
    const float* key   = (const float*)d_in[1];
    const float* value = (const float*)d_in[2];
    const float* Wq    = (const float*)d_in[3];
    const float* bq    = (const float*)d_in[4];
    const float* Wk    = (const float*)d_in[5];
    const float* bk    = (const float*)d_in[6];
    const float* Wv    = (const float*)d_in[7];
    const float* bv    = (const float*)d_in[8];
    const float* Wo    = (const float*)d_in[9];
    const float* bo    = (const float*)d_in[10];

    float* out  = (float*)d_out;                          // (B,S,D)
    float* attn = out + (size_t)B_ * S_ * D_;             // (B,H,S,S)

    float *q, *k, *v, *ctx;
    cudaGetSymbolAddress((void**)&q,   g_q);
    cudaGetSymbolAddress((void**)&k,   g_k);
    cudaGetSymbolAddress((void**)&v,   g_v);
    cudaGetSymbolAddress((void**)&ctx, g_ctx);

    const int M = B_ * S_;   // 4096
    const int N = D_;        // 1024
    const int K = D_;        // 1024
    dim3 ggrid(N / 128, M / 128);

    sgemm_xwt<<<ggrid, 256>>>(query, Wq, bq, q, M, N, K);
    sgemm_xwt<<<ggrid, 256>>>(key,   Wk, bk, k, M, N, K);
    sgemm_xwt<<<ggrid, 256>>>(value, Wv, bv, v, M, N, K);

    dim3 qkgrid(S_ / 128, S_ / 128, B_ * H_);
    qk_scores<<<qkgrid, 256>>>(q, k, attn);

    softmax_rows<<<B_ * H_ * S_, 256>>>(attn);

    dim3 pvgrid(S_ / 128, B_ * H_);
    pv_gemm<<<pvgrid, 256>>>(attn, v, ctx);

    sgemm_xwt<<<ggrid, 256>>>(ctx, Wo, bo, out, M, N, K);
}

// round 3
// speedup vs baseline: 4.2092x; 1.7256x over previous
#include <cuda_runtime.h>
#include <math.h>

// Problem constants
#define B_ 2
#define S_ 2048
#define D_ 1024
#define H_ 16
#define DK_ 64

// ---------------- scratch (no cudaMalloc allowed) ----------------
__device__ float g_q[(size_t)B_ * S_ * D_];
__device__ float g_k[(size_t)B_ * S_ * D_];
__device__ float g_v[(size_t)B_ * S_ * D_];
__device__ float g_ctx[(size_t)B_ * S_ * D_];

// ---------------- TF32 helpers ----------------
__device__ __forceinline__ unsigned f2tf32(float x) {
    unsigned r;
    asm("cvt.rna.tf32.f32 %0, %1;" : "=r"(r) : "f"(x));
    return r;
}

__device__ __forceinline__ void mma_tf32(float c[4],
    unsigned a0, unsigned a1, unsigned a2, unsigned a3,
    unsigned b0, unsigned b1)
{
    asm volatile(
        "mma.sync.aligned.m16n8k8.row.col.f32.tf32.tf32.f32 "
        "{%0,%1,%2,%3}, {%4,%5,%6,%7}, {%8,%9}, {%0,%1,%2,%3};"
        : "+f"(c[0]), "+f"(c[1]), "+f"(c[2]), "+f"(c[3])
        : "r"(a0), "r"(a1), "r"(a2), "r"(a3), "r"(b0), "r"(b1));
}

// ================= generic TF32 NT GEMM =================
// C[M,N] = scale * A[M,K] @ B[N,K]^T (+ bias[N])
// Per-z offsets: off = (z>>4)*batchStride + (z&15)*headStride.
// Block 128x128, 128 threads (4 warps, 2x2 grid of 64x64 warp tiles), BK=16.
template<int KDIM, bool HAS_BIAS>
__global__ __launch_bounds__(128) void gemm_tf32_nt(
    const float* __restrict__ A, const float* __restrict__ Bm,
    const float* __restrict__ bias, float* __restrict__ C,
    int lda, int ldb, int ldc,
    size_t aB, size_t aH, size_t bB, size_t bH, size_t cB, size_t cH,
    float scale)
{
    __shared__ unsigned As[2][16][136];
    __shared__ unsigned Bs[2][16][136];

    const int tid  = threadIdx.x;
    const int lane = tid & 31;
    const int wid  = tid >> 5;
    const int wm   = wid & 1;            // 0..1 -> 64-row half
    const int wn   = wid >> 1;           // 0..1 -> 64-col half
    const int bm   = blockIdx.y * 128;
    const int bn   = blockIdx.x * 128;
    const int z    = blockIdx.z;
    const int zb   = z >> 4, zh = z & 15;

    const float* Ap = A + zb * aB + zh * aH + (size_t)(bm + tid) * lda;
    const float* Bp = Bm + zb * bB + zh * bH + (size_t)(bn + tid) * ldb;

    float acc[4][8][4];
#pragma unroll
    for (int i = 0; i < 4; i++)
#pragma unroll
        for (int j = 0; j < 8; j++)
#pragma unroll
            for (int e = 0; e < 4; e++) acc[i][j][e] = 0.f;

    float4 ar[4], br[4];
#pragma unroll
    for (int f = 0; f < 4; f++) {
        ar[f] = *(const float4*)(Ap + f * 4);
        br[f] = *(const float4*)(Bp + f * 4);
    }
#pragma unroll
    for (int f = 0; f < 4; f++) {
        As[0][f*4+0][tid] = f2tf32(ar[f].x);
        As[0][f*4+1][tid] = f2tf32(ar[f].y);
        As[0][f*4+2][tid] = f2tf32(ar[f].z);
        As[0][f*4+3][tid] = f2tf32(ar[f].w);
        Bs[0][f*4+0][tid] = f2tf32(br[f].x);
        Bs[0][f*4+1][tid] = f2tf32(br[f].y);
        Bs[0][f*4+2][tid] = f2tf32(br[f].z);
        Bs[0][f*4+3][tid] = f2tf32(br[f].w);
    }
    __syncthreads();

    const int NIT = KDIM / 16;
    const int mg  = wm * 64 + (lane >> 2);
    const int ng  = wn * 64 + (lane >> 2);
    const int kl  = lane & 3;

    for (int it = 0; it < NIT; it++) {
        const int cur = it & 1;
        if (it + 1 < NIT) {
            const int k0 = (it + 1) * 16;
#pragma unroll
            for (int f = 0; f < 4; f++) {
                ar[f] = *(const float4*)(Ap + k0 + f * 4);
                br[f] = *(const float4*)(Bp + k0 + f * 4);
            }
        }
#pragma unroll
        for (int s = 0; s < 2; s++) {
            const int kb = s * 8 + kl;
            unsigned af[4][4];
#pragma unroll
            for (int i = 0; i < 4; i++) {
                af[i][0] = As[cur][kb    ][mg + i * 16];
                af[i][1] = As[cur][kb    ][mg + i * 16 + 8];
                af[i][2] = As[cur][kb + 4][mg + i * 16];
                af[i][3] = As[cur][kb + 4][mg + i * 16 + 8];
            }
#pragma unroll
            for (int j = 0; j < 8; j++) {
                unsigned b0 = Bs[cur][kb    ][ng + j * 8];
                unsigned b1 = Bs[cur][kb + 4][ng + j * 8];
#pragma unroll
                for (int i = 0; i < 4; i++)
                    mma_tf32(acc[i][j], af[i][0], af[i][1], af[i][2], af[i][3], b0, b1);
            }
        }
        if (it + 1 < NIT) {
            const int nxt = cur ^ 1;
#pragma unroll
            for (int f = 0; f < 4; f++) {
                As[nxt][f*4+0][tid] = f2tf32(ar[f].x);
                As[nxt][f*4+1][tid] = f2tf32(ar[f].y);
                As[nxt][f*4+2][tid] = f2tf32(ar[f].z);
                As[nxt][f*4+3][tid] = f2tf32(ar[f].w);
                Bs[nxt][f*4+0][tid] = f2tf32(br[f].x);
                Bs[nxt][f*4+1][tid] = f2tf32(br[f].y);
                Bs[nxt][f*4+2][tid] = f2tf32(br[f].z);
                Bs[nxt][f*4+3][tid] = f2tf32(br[f].w);
            }
            __syncthreads();
        }
    }

    // epilogue
    float* Cp = C + zb * cB + zh * cH;
    const int row0 = bm + wm * 64 + (lane >> 2);
    const int col0 = bn + wn * 64 + (lane & 3) * 2;

    float2 bvj[8];
    if (HAS_BIAS) {
#pragma unroll
        for (int j = 0; j < 8; j++)
            bvj[j] = *(const float2*)&bias[col0 + j * 8];
    }

#pragma unroll
    for (int i = 0; i < 4; i++) {
#pragma unroll
        for (int j = 0; j < 8; j++) {
            const int r = row0 + i * 16;
            const int c = col0 + j * 8;
            float2 lo, hi;
            lo.x = acc[i][j][0] * scale;
            lo.y = acc[i][j][1] * scale;
            hi.x = acc[i][j][2] * scale;
            hi.y = acc[i][j][3] * scale;
            if (HAS_BIAS) {
                lo.x += bvj[j].x; lo.y += bvj[j].y;
                hi.x += bvj[j].x; hi.y += bvj[j].y;
            }
            *(float2*)&Cp[(size_t)r * ldc + c]       = lo;
            *(float2*)&Cp[(size_t)(r + 8) * ldc + c] = hi;
        }
    }
}

// ================= PV: ctx = P @ V (TF32) =================
// Per (b,h): C[2048,64] = P[2048,2048] @ V[2048,64]
// Block 128(M)x64(N), 128 threads (4 warps, 2x2, warp tile 64x32), BK=16.
__global__ __launch_bounds__(128) void pv_tf32(
    const float* __restrict__ attn, const float* __restrict__ Vg,
    float* __restrict__ ctx)
{
    __shared__ unsigned Ps[2][16][136];
    __shared__ unsigned Vs[2][16][72];

    const int tid  = threadIdx.x;
    const int lane = tid & 31;
    const int wid  = tid >> 5;
    const int wm   = wid & 1;         // 64-row half
    const int wn   = wid >> 1;        // 32-col half
    const int bm   = blockIdx.y * 128;
    const int z    = blockIdx.z;
    const int zb   = z >> 4, zh = z & 15;

    const float* P = attn + (size_t)z * S_ * S_ + (size_t)(bm + tid) * S_;
    const float* V = Vg + (size_t)zb * S_ * D_ + (size_t)zh * DK_;
    float* Cc = ctx + (size_t)zb * S_ * D_ + (size_t)zh * DK_;

    const int vr = tid >> 3;              // 0..15
    const int vc = (tid & 7) * 8;         // 0..56
    const float* Vp = V + (size_t)vr * D_ + vc;

    float acc[4][4][4];
#pragma unroll
    for (int i = 0; i < 4; i++)
#pragma unroll
        for (int j = 0; j < 4; j++)
#pragma unroll
            for (int e = 0; e < 4; e++) acc[i][j][e] = 0.f;

    float4 pr[4], vv[2];
#pragma unroll
    for (int f = 0; f < 4; f++) pr[f] = *(const float4*)(P + f * 4);
    vv[0] = *(const float4*)(Vp);
    vv[1] = *(const float4*)(Vp + 4);
#pragma unroll
    for (int f = 0; f < 4; f++) {
        Ps[0][f*4+0][tid] = f2tf32(pr[f].x);
        Ps[0][f*4+1][tid] = f2tf32(pr[f].y);
        Ps[0][f*4+2][tid] = f2tf32(pr[f].z);
        Ps[0][f*4+3][tid] = f2tf32(pr[f].w);
    }
    Vs[0][vr][vc+0] = f2tf32(vv[0].x); Vs[0][vr][vc+1] = f2tf32(vv[0].y);
    Vs[0][vr][vc+2] = f2tf32(vv[0].z); Vs[0][vr][vc+3] = f2tf32(vv[0].w);
    Vs[0][vr][vc+4] = f2tf32(vv[1].x); Vs[0][vr][vc+5] = f2tf32(vv[1].y);
    Vs[0][vr][vc+6] = f2tf32(vv[1].z); Vs[0][vr][vc+7] = f2tf32(vv[1].w);
    __syncthreads();

    const int NIT = S_ / 16;
    const int mg  = wm * 64 + (lane >> 2);
    const int ng  = wn * 32 + (lane >> 2);
    const int kl  = lane & 3;

    for (int it = 0; it < NIT; it++) {
        const int cur = it & 1;
        if (it + 1 < NIT) {
            const int k0 = (it + 1) * 16;
#pragma unroll
            for (int f = 0; f < 4; f++) pr[f] = *(const float4*)(P + k0 + f * 4);
            vv[0] = *(const float4*)(Vp + (size_t)k0 * D_);
            vv[1] = *(const float4*)(Vp + (size_t)k0 * D_ + 4);
        }
#pragma unroll
        for (int s = 0; s < 2; s++) {
            const int kb = s * 8 + kl;
            unsigned af[4][4];
#pragma unroll
            for (int i = 0; i < 4; i++) {
                af[i][0] = Ps[cur][kb    ][mg + i * 16];
                af[i][1] = Ps[cur][kb    ][mg + i * 16 + 8];
                af[i][2] = Ps[cur][kb + 4][mg + i * 16];
                af[i][3] = Ps[cur][kb + 4][mg + i * 16 + 8];
            }
#pragma unroll
            for (int j = 0; j < 4; j++) {
                unsigned b0 = Vs[cur][kb    ][ng + j * 8];
                unsigned b1 = Vs[cur][kb + 4][ng + j * 8];
#pragma unroll
                for (int i = 0; i < 4; i++)
                    mma_tf32(acc[i][j], af[i][0], af[i][1], af[i][2], af[i][3], b0, b1);
            }
        }
        if (it + 1 < NIT) {
            const int nxt = cur ^ 1;
#pragma unroll
            for (int f = 0; f < 4; f++) {
                Ps[nxt][f*4+0][tid] = f2tf32(pr[f].x);
                Ps[nxt][f*4+1][tid] = f2tf32(pr[f].y);
                Ps[nxt][f*4+2][tid] = f2tf32(pr[f].z);
                Ps[nxt][f*4+3][tid] = f2tf32(pr[f].w);
            }
            Vs[nxt][vr][vc+0] = f2tf32(vv[0].x); Vs[nxt][vr][vc+1] = f2tf32(vv[0].y);
            Vs[nxt][vr][vc+2] = f2tf32(vv[0].z); Vs[nxt][vr][vc+3] = f2tf32(vv[0].w);
            Vs[nxt][vr][vc+4] = f2tf32(vv[1].x); Vs[nxt][vr][vc+5] = f2tf32(vv[1].y);
            Vs[nxt][vr][vc+6] = f2tf32(vv[1].z); Vs[nxt][vr][vc+7] = f2tf32(vv[1].w);
            __syncthreads();
        }
    }

    const int row0 = bm + wm * 64 + (lane >> 2);
    const int col0 = wn * 32 + (lane & 3) * 2;
#pragma unroll
    for (int i = 0; i < 4; i++) {
#pragma unroll
        for (int j = 0; j < 4; j++) {
            const int r = row0 + i * 16;
            const int c = col0 + j * 8;
            float2 lo, hi;
            lo.x = acc[i][j][0]; lo.y = acc[i][j][1];
            hi.x = acc[i][j][2]; hi.y = acc[i][j][3];
            *(float2*)&Cc[(size_t)r * D_ + c]       = lo;
            *(float2*)&Cc[(size_t)(r + 8) * D_ + c] = hi;
        }
    }
}

// ---------------- streaming row softmax (in place) ----------------
__global__ __launch_bounds__(256) void softmax_rows(float* __restrict__ attn)
{
    __shared__ float redmax[8];
    __shared__ float redsum[8];

    size_t row = blockIdx.x;
    float* p = attn + row * (size_t)S_;
    int tid = threadIdx.x;
    int lane = tid & 31, warp = tid >> 5;

    float4 v0 = ((const float4*)p)[tid];
    float4 v1 = ((const float4*)p)[tid + 256];

    float mx = fmaxf(fmaxf(fmaxf(v0.x, v0.y), fmaxf(v0.z, v0.w)),
                     fmaxf(fmaxf(v1.x, v1.y), fmaxf(v1.z, v1.w)));
#pragma unroll
    for (int o = 16; o > 0; o >>= 1)
        mx = fmaxf(mx, __shfl_xor_sync(0xffffffffu, mx, o));
    if (lane == 0) redmax[warp] = mx;
    __syncthreads();
    mx = redmax[0];
#pragma unroll
    for (int w = 1; w < 8; w++) mx = fmaxf(mx, redmax[w]);

    v0.x = __expf(v0.x - mx); v0.y = __expf(v0.y - mx);
    v0.z = __expf(v0.z - mx); v0.w = __expf(v0.w - mx);
    v1.x = __expf(v1.x - mx); v1.y = __expf(v1.y - mx);
    v1.z = __expf(v1.z - mx); v1.w = __expf(v1.w - mx);

    float sum = (v0.x + v0.y) + (v0.z + v0.w) + (v1.x + v1.y) + (v1.z + v1.w);
#pragma unroll
    for (int o = 16; o > 0; o >>= 1)
        sum += __shfl_xor_sync(0xffffffffu, sum, o);
    if (lane == 0) redsum[warp] = sum;
    __syncthreads();
    sum = redsum[0];
#pragma unroll
    for (int w = 1; w < 8; w++) sum += redsum[w];

    float inv = 1.f / sum;
    v0.x *= inv; v0.y *= inv; v0.z *= inv; v0.w *= inv;
    v1.x *= inv; v1.y *= inv; v1.z *= inv; v1.w *= inv;

    ((float4*)p)[tid]       = v0;
    ((float4*)p)[tid + 256] = v1;
}

// ---------------- launch ----------------
extern "C" void kernel_launch(void* const* d_in, const int* in_sizes, int n_in,
                              void* d_out, int out_size)
{
    const float* query = (const float*)d_in[0];
    const float* key   = (const float*)d_in[1];
    const float* value = (const float*)d_in[2];
    const float* Wq    = (const float*)d_in[3];
    const float* bq    = (const float*)d_in[4];
    const float* Wk    = (const float*)d_in[5];
    const float* bk    = (const float*)d_in[6];
    const float* Wv    = (const float*)d_in[7];
    const float* bv    = (const float*)d_in[8];
    const float* Wo    = (const float*)d_in[9];
    const float* bo    = (const float*)d_in[10];

    float* out  = (float*)d_out;                          // (B,S,D)
    float* attn = out + (size_t)B_ * S_ * D_;             // (B,H,S,S)

    float *q, *k, *v, *ctx;
    cudaGetSymbolAddress((void**)&q,   g_q);
    cudaGetSymbolAddress((void**)&k,   g_k);
    cudaGetSymbolAddress((void**)&v,   g_v);
    cudaGetSymbolAddress((void**)&ctx, g_ctx);

    // Projections: C[4096,1024] = X @ W^T + b
    dim3 pgrid(D_ / 128, (B_ * S_) / 128, 1);
    gemm_tf32_nt<D_, true><<<pgrid, 128>>>(query, Wq, bq, q,
        D_, D_, D_, 0, 0, 0, 0, 0, 0, 1.f);
    gemm_tf32_nt<D_, true><<<pgrid, 128>>>(key, Wk, bk, k,
        D_, D_, D_, 0, 0, 0, 0, 0, 0, 1.f);
    gemm_tf32_nt<D_, true><<<pgrid, 128>>>(value, Wv, bv, v,
        D_, D_, D_, 0, 0, 0, 0, 0, 0, 1.f);

    // QK^T: per (b,h): scores[2048,2048] = 0.125 * q @ k^T
    dim3 qkgrid(S_ / 128, S_ / 128, B_ * H_);
    gemm_tf32_nt<DK_, false><<<qkgrid, 128>>>(q, k, nullptr, attn,
        D_, D_, S_,
        (size_t)S_ * D_, DK_,
        (size_t)S_ * D_, DK_,
        (size_t)H_ * S_ * S_, (size_t)S_ * S_,
        0.125f);

    softmax_rows<<<B_ * H_ * S_, 256>>>(attn);

    dim3 pvgrid(1, S_ / 128, B_ * H_);
    pv_tf32<<<pvgrid, 128>>>(attn, v, ctx);

    gemm_tf32_nt<D_, true><<<pgrid, 128>>>(ctx, Wo, bo, out,
        D_, D_, D_, 0, 0, 0, 0, 0, 0, 1.f);
}

// round 4
// speedup vs baseline: 5.0350x; 1.1962x over previous
#include <cuda_runtime.h>
#include <math.h>

// Problem constants
#define B_ 2
#define S_ 2048
#define D_ 1024
#define H_ 16
#define DK_ 64

// ---------------- scratch (no cudaMalloc allowed) ----------------
__device__ float g_q[(size_t)B_ * S_ * D_];
__device__ float g_k[(size_t)B_ * S_ * D_];
__device__ float g_v[(size_t)B_ * S_ * D_];
__device__ float g_ctx[(size_t)B_ * S_ * D_];
// per-row exp partial sums: [z][row][16 bn-tiles * 4 wn] = 64 partials/row
__device__ float g_partial[(size_t)B_ * H_ * S_ * 64];

// ---------------- TF32 helpers ----------------
__device__ __forceinline__ unsigned f2tf32(float x) {
    unsigned r;
    asm("cvt.rna.tf32.f32 %0, %1;" : "=r"(r) : "f"(x));
    return r;
}

__device__ __forceinline__ void mma_tf32(float c[4],
    unsigned a0, unsigned a1, unsigned a2, unsigned a3,
    unsigned b0, unsigned b1)
{
    asm volatile(
        "mma.sync.aligned.m16n8k8.row.col.f32.tf32.tf32.f32 "
        "{%0,%1,%2,%3}, {%4,%5,%6,%7}, {%8,%9}, {%0,%1,%2,%3};"
        : "+f"(c[0]), "+f"(c[1]), "+f"(c[2]), "+f"(c[3])
        : "r"(a0), "r"(a1), "r"(a2), "r"(a3), "r"(b0), "r"(b1));
}

__device__ __forceinline__ void sts4(unsigned (*s)[136], int k, int r, float4 v) {
    s[k + 0][r] = f2tf32(v.x);
    s[k + 1][r] = f2tf32(v.y);
    s[k + 2][r] = f2tf32(v.z);
    s[k + 3][r] = f2tf32(v.w);
}

// ================= generic TF32 NT GEMM =================
// C[M,N] = scale * A[M,K] @ B[N,K]^T (+ bias[N]), or exp-epilogue for QK.
// Block 128x128, 256 threads (8 warps as 2x4 grid of 64x32 warp tiles), BK=16.
template<int KDIM, bool HAS_BIAS, bool EXP_MODE>
__global__ __launch_bounds__(256, 2) void gemm_tf32(
    const float* __restrict__ A, const float* __restrict__ Bm,
    const float* __restrict__ bias, float* __restrict__ C,
    int lda, int ldb, int ldc,
    size_t aB, size_t aH, size_t bB, size_t bH, size_t cB, size_t cH,
    float scale, float* __restrict__ partial)
{
    __shared__ unsigned As[2][16][136];
    __shared__ unsigned Bs[2][16][136];

    const int tid  = threadIdx.x;
    const int lane = tid & 31;
    const int wid  = tid >> 5;
    const int wm   = wid & 1;            // 0..1 -> 64-row half
    const int wn   = wid >> 1;           // 0..3 -> 32-col quarter
    const int bm   = blockIdx.y * 128;
    const int bn   = blockIdx.x * 128;
    const int z    = blockIdx.z;
    const int zb   = z >> 4, zh = z & 15;

    const int arow = tid >> 1;           // 0..127
    const int ak   = (tid & 1) * 8;      // 0 or 8
    const float* Ap = A + zb * aB + zh * aH + (size_t)(bm + arow) * lda + ak;
    const float* Bp = Bm + zb * bB + zh * bH + (size_t)(bn + arow) * ldb + ak;

    float acc[4][4][4];
#pragma unroll
    for (int i = 0; i < 4; i++)
#pragma unroll
        for (int j = 0; j < 4; j++)
#pragma unroll
            for (int e = 0; e < 4; e++) acc[i][j][e] = 0.f;

    float4 a0, a1, b0, b1;
    a0 = *(const float4*)(Ap);
    a1 = *(const float4*)(Ap + 4);
    b0 = *(const float4*)(Bp);
    b1 = *(const float4*)(Bp + 4);
    sts4(As[0], ak, arow, a0);
    sts4(As[0], ak + 4, arow, a1);
    sts4(Bs[0], ak, arow, b0);
    sts4(Bs[0], ak + 4, arow, b1);
    __syncthreads();

    const int NIT = KDIM / 16;
    const int mg  = wm * 64 + (lane >> 2);
    const int ng  = wn * 32 + (lane >> 2);
    const int kl  = lane & 3;

    for (int it = 0; it < NIT; it++) {
        const int cur = it & 1;
        if (it + 1 < NIT) {
            const int k0 = (it + 1) * 16;
            a0 = *(const float4*)(Ap + k0);
            a1 = *(const float4*)(Ap + k0 + 4);
            b0 = *(const float4*)(Bp + k0);
            b1 = *(const float4*)(Bp + k0 + 4);
        }
#pragma unroll
        for (int s = 0; s < 2; s++) {
            const int kb = s * 8 + kl;
            unsigned af[4][4];
#pragma unroll
            for (int i = 0; i < 4; i++) {
                af[i][0] = As[cur][kb    ][mg + i * 16];
                af[i][1] = As[cur][kb    ][mg + i * 16 + 8];
                af[i][2] = As[cur][kb + 4][mg + i * 16];
                af[i][3] = As[cur][kb + 4][mg + i * 16 + 8];
            }
            unsigned bf[4][2];
#pragma unroll
            for (int j = 0; j < 4; j++) {
                bf[j][0] = Bs[cur][kb    ][ng + j * 8];
                bf[j][1] = Bs[cur][kb + 4][ng + j * 8];
            }
#pragma unroll
            for (int j = 0; j < 4; j++)
#pragma unroll
                for (int i = 0; i < 4; i++)
                    mma_tf32(acc[i][j], af[i][0], af[i][1], af[i][2], af[i][3],
                             bf[j][0], bf[j][1]);
        }
        if (it + 1 < NIT) {
            const int nxt = cur ^ 1;
            sts4(As[nxt], ak, arow, a0);
            sts4(As[nxt], ak + 4, arow, a1);
            sts4(Bs[nxt], ak, arow, b0);
            sts4(Bs[nxt], ak + 4, arow, b1);
            __syncthreads();
        }
    }

    // epilogue
    float* Cp = C + zb * cB + zh * cH;
    const int rl   = wm * 64 + (lane >> 2);      // local row within 128-tile
    const int col0 = bn + wn * 32 + (lane & 3) * 2;

    if (EXP_MODE) {
        // write exp(scale*s); accumulate per-row partial sums over this warp's 32 cols
#pragma unroll
        for (int i = 0; i < 4; i++) {
            const int rlo = bm + rl + i * 16;
            const int rhi = rlo + 8;
            float pl = 0.f, ph = 0.f;
#pragma unroll
            for (int j = 0; j < 4; j++) {
                float e0 = __expf(acc[i][j][0] * scale);
                float e1 = __expf(acc[i][j][1] * scale);
                float e2 = __expf(acc[i][j][2] * scale);
                float e3 = __expf(acc[i][j][3] * scale);
                float2 lo; lo.x = e0; lo.y = e1;
                float2 hi; hi.x = e2; hi.y = e3;
                *(float2*)&Cp[(size_t)rlo * ldc + col0 + j * 8] = lo;
                *(float2*)&Cp[(size_t)rhi * ldc + col0 + j * 8] = hi;
                pl += e0 + e1;
                ph += e2 + e3;
            }
            // reduce across the 4 lanes of the quad (lane&3 = 0..3)
            pl += __shfl_xor_sync(0xffffffffu, pl, 1);
            pl += __shfl_xor_sync(0xffffffffu, pl, 2);
            ph += __shfl_xor_sync(0xffffffffu, ph, 1);
            ph += __shfl_xor_sync(0xffffffffu, ph, 2);
            if ((lane & 3) == 0) {
                partial[((size_t)z * S_ + rlo) * 64 + blockIdx.x * 4 + wn] = pl;
                partial[((size_t)z * S_ + rhi) * 64 + blockIdx.x * 4 + wn] = ph;
            }
        }
    } else {
        float2 bvj[4];
        if (HAS_BIAS) {
#pragma unroll
            for (int j = 0; j < 4; j++)
                bvj[j] = *(const float2*)&bias[col0 + j * 8];
        }
#pragma unroll
        for (int i = 0; i < 4; i++) {
#pragma unroll
            for (int j = 0; j < 4; j++) {
                const int r = bm + rl + i * 16;
                const int c = col0 + j * 8;
                float2 lo, hi;
                lo.x = acc[i][j][0] * scale;
                lo.y = acc[i][j][1] * scale;
                hi.x = acc[i][j][2] * scale;
                hi.y = acc[i][j][3] * scale;
                if (HAS_BIAS) {
                    lo.x += bvj[j].x; lo.y += bvj[j].y;
                    hi.x += bvj[j].x; hi.y += bvj[j].y;
                }
                *(float2*)&Cp[(size_t)r * ldc + c]       = lo;
                *(float2*)&Cp[(size_t)(r + 8) * ldc + c] = hi;
            }
        }
    }
}

// ================= PV: normalize attn in place + ctx = P @ V =================
// Block 128(M)x64(N), 256 threads (8 warps as 4x2 grid of 32x32 warp tiles), BK=16.
// Prologue: reduce 64 exp-partials per row -> 1/rowsum.
// Main loop streams exp-scores, multiplies by inv (final attn value), writes it
// back in place, and feeds it to tf32 MMA against V.
__global__ __launch_bounds__(256, 2) void pv_tf32(
    float* __restrict__ attn, const float* __restrict__ Vg,
    float* __restrict__ ctx, const float* __restrict__ partial)
{
    __shared__ unsigned Ps[2][16][136];
    __shared__ unsigned Vs[2][16][72];
    __shared__ float s_inv[128];

    const int tid  = threadIdx.x;
    const int lane = tid & 31;
    const int wid  = tid >> 5;
    const int wm   = wid & 3;         // 0..3 -> 32-row quarter
    const int wn   = wid >> 2;        // 0..1 -> 32-col half
    const int bm   = blockIdx.x * 128;
    const int z    = blockIdx.y;
    const int zb   = z >> 4, zh = z & 15;

    // ---- prologue: per-row inverse sums ----
    {
        const int r = tid >> 1;
        const float* pp = partial + ((size_t)z * S_ + bm + r) * 64 + (tid & 1) * 32;
        float s = 0.f;
#pragma unroll
        for (int f = 0; f < 8; f++) {
            float4 u = ((const float4*)pp)[f];
            s += (u.x + u.y) + (u.z + u.w);
        }
        s += __shfl_xor_sync(0xffffffffu, s, 1);
        if (!(tid & 1)) s_inv[r] = 1.f / s;
    }
    __syncthreads();

    const int prow = tid >> 1;            // 0..127
    const int pk   = (tid & 1) * 8;
    float* P = attn + (size_t)z * S_ * S_ + (size_t)(bm + prow) * S_ + pk;
    const float inv = s_inv[prow];

    const int vr = tid >> 4;              // 0..15 (k within tile)
    const int vc = (tid & 15) * 4;        // 0..60
    const float* Vp = Vg + (size_t)zb * S_ * D_ + (size_t)zh * DK_
                      + (size_t)vr * D_ + vc;

    float acc[2][4][4];
#pragma unroll
    for (int i = 0; i < 2; i++)
#pragma unroll
        for (int j = 0; j < 4; j++)
#pragma unroll
            for (int e = 0; e < 4; e++) acc[i][j][e] = 0.f;

    float4 p0, p1, vv;
    // tile 0
    p0 = *(const float4*)(P);
    p1 = *(const float4*)(P + 4);
    p0.x *= inv; p0.y *= inv; p0.z *= inv; p0.w *= inv;
    p1.x *= inv; p1.y *= inv; p1.z *= inv; p1.w *= inv;
    *(float4*)(P)     = p0;    // final normalized attn
    *(float4*)(P + 4) = p1;
    vv = *(const float4*)(Vp);
    sts4(Ps[0], pk, prow, p0);
    sts4(Ps[0], pk + 4, prow, p1);
    Vs[0][vr][vc + 0] = f2tf32(vv.x);
    Vs[0][vr][vc + 1] = f2tf32(vv.y);
    Vs[0][vr][vc + 2] = f2tf32(vv.z);
    Vs[0][vr][vc + 3] = f2tf32(vv.w);
    __syncthreads();

    const int NIT = S_ / 16;
    const int mg  = wm * 32 + (lane >> 2);
    const int ng  = wn * 32 + (lane >> 2);
    const int kl  = lane & 3;

    for (int it = 0; it < NIT; it++) {
        const int cur = it & 1;
        if (it + 1 < NIT) {
            const int k0 = (it + 1) * 16;
            p0 = *(const float4*)(P + k0);
            p1 = *(const float4*)(P + k0 + 4);
            p0.x *= inv; p0.y *= inv; p0.z *= inv; p0.w *= inv;
            p1.x *= inv; p1.y *= inv; p1.z *= inv; p1.w *= inv;
            *(float4*)(P + k0)     = p0;
            *(float4*)(P + k0 + 4) = p1;
            vv = *(const float4*)(Vp + (size_t)k0 * D_);
        }
#pragma unroll
        for (int s = 0; s < 2; s++) {
            const int kb = s * 8 + kl;
            unsigned af[2][4];
#pragma unroll
            for (int i = 0; i < 2; i++) {
                af[i][0] = Ps[cur][kb    ][mg + i * 16];
                af[i][1] = Ps[cur][kb    ][mg + i * 16 + 8];
                af[i][2] = Ps[cur][kb + 4][mg + i * 16];
                af[i][3] = Ps[cur][kb + 4][mg + i * 16 + 8];
            }
            unsigned bf[4][2];
#pragma unroll
            for (int j = 0; j < 4; j++) {
                bf[j][0] = Vs[cur][kb    ][ng + j * 8];
                bf[j][1] = Vs[cur][kb + 4][ng + j * 8];
            }
#pragma unroll
            for (int j = 0; j < 4; j++)
#pragma unroll
                for (int i = 0; i < 2; i++)
                    mma_tf32(acc[i][j], af[i][0], af[i][1], af[i][2], af[i][3],
                             bf[j][0], bf[j][1]);
        }
        if (it + 1 < NIT) {
            const int nxt = cur ^ 1;
            sts4(Ps[nxt], pk, prow, p0);
            sts4(Ps[nxt], pk + 4, prow, p1);
            Vs[nxt][vr][vc + 0] = f2tf32(vv.x);
            Vs[nxt][vr][vc + 1] = f2tf32(vv.y);
            Vs[nxt][vr][vc + 2] = f2tf32(vv.z);
            Vs[nxt][vr][vc + 3] = f2tf32(vv.w);
            __syncthreads();
        }
    }

    float* Cc = ctx + (size_t)zb * S_ * D_ + (size_t)zh * DK_;
    const int row0 = bm + wm * 32 + (lane >> 2);
    const int col0 = wn * 32 + (lane & 3) * 2;
#pragma unroll
    for (int i = 0; i < 2; i++) {
#pragma unroll
        for (int j = 0; j < 4; j++) {
            const int r = row0 + i * 16;
            const int c = col0 + j * 8;
            float2 lo, hi;
            lo.x = acc[i][j][0]; lo.y = acc[i][j][1];
            hi.x = acc[i][j][2]; hi.y = acc[i][j][3];
            *(float2*)&Cc[(size_t)r * D_ + c]       = lo;
            *(float2*)&Cc[(size_t)(r + 8) * D_ + c] = hi;
        }
    }
}

// ---------------- launch ----------------
extern "C" void kernel_launch(void* const* d_in, const int* in_sizes, int n_in,
                              void* d_out, int out_size)
{
    const float* query = (const float*)d_in[0];
    const float* key   = (const float*)d_in[1];
    const float* value = (const float*)d_in[2];
    const float* Wq    = (const float*)d_in[3];
    const float* bq    = (const float*)d_in[4];
    const float* Wk    = (const float*)d_in[5];
    const float* bk    = (const float*)d_in[6];
    const float* Wv    = (const float*)d_in[7];
    const float* bv    = (const float*)d_in[8];
    const float* Wo    = (const float*)d_in[9];
    const float* bo    = (const float*)d_in[10];

    float* out  = (float*)d_out;                          // (B,S,D)
    float* attn = out + (size_t)B_ * S_ * D_;             // (B,H,S,S)

    float *q, *k, *v, *ctx, *part;
    cudaGetSymbolAddress((void**)&q,    g_q);
    cudaGetSymbolAddress((void**)&k,    g_k);
    cudaGetSymbolAddress((void**)&v,    g_v);
    cudaGetSymbolAddress((void**)&ctx,  g_ctx);
    cudaGetSymbolAddress((void**)&part, g_partial);

    // Projections: C[4096,1024] = X @ W^T + b
    dim3 pgrid(D_ / 128, (B_ * S_) / 128, 1);
    gemm_tf32<D_, true, false><<<pgrid, 256>>>(query, Wq, bq, q,
        D_, D_, D_, 0, 0, 0, 0, 0, 0, 1.f, nullptr);
    gemm_tf32<D_, true, false><<<pgrid, 256>>>(key, Wk, bk, k,
        D_, D_, D_, 0, 0, 0, 0, 0, 0, 1.f, nullptr);
    gemm_tf32<D_, true, false><<<pgrid, 256>>>(value, Wv, bv, v,
        D_, D_, D_, 0, 0, 0, 0, 0, 0, 1.f, nullptr);

    // QK^T -> exp(scores) + row partial sums
    dim3 qkgrid(S_ / 128, S_ / 128, B_ * H_);
    gemm_tf32<DK_, false, true><<<qkgrid, 256>>>(q, k, nullptr, attn,
        D_, D_, S_,
        (size_t)S_ * D_, DK_,
        (size_t)S_ * D_, DK_,
        (size_t)H_ * S_ * S_, (size_t)S_ * S_,
        0.125f, part);

    // normalize attn in place + ctx = P @ V
    dim3 pvgrid(S_ / 128, B_ * H_);
    pv_tf32<<<pvgrid, 256>>>(attn, v, ctx, part);

    // output projection
    gemm_tf32<D_, true, false><<<pgrid, 256>>>(ctx, Wo, bo, out,
        D_, D_, D_, 0, 0, 0, 0, 0, 0, 1.f, nullptr);
}